// round 4
// baseline (speedup 1.0000x reference)
#include <cuda_runtime.h>
#include <cstdint>

#define L        8192
#define CHN      16
#define BATCH    32
#define NSTEPS   100
#define HSTEP    0.01f
#define TILE     1024
#define COMMIT   1008
#define NT       9
#define NTHREADS 256

typedef unsigned long long ull;

__device__ float g_scratch[(size_t)BATCH * CHN * L];

__device__ __forceinline__ ull pk2(float lo, float hi) {
    ull r; asm("mov.b64 %0, {%1,%2};" : "=l"(r) : "f"(lo), "f"(hi)); return r;
}
__device__ __forceinline__ void upk2(ull a, float& lo, float& hi) {
    asm("mov.b64 {%0,%1}, %2;" : "=f"(lo), "=f"(hi) : "l"(a));
}
__device__ __forceinline__ void fma2(ull &acc, ull a, ull b) {
    asm("fma.rn.f32x2 %0, %1, %2, %0;" : "+l"(acc) : "l"(a), "l"(b));
}
__device__ __forceinline__ ull fma2g(ull a, ull b, ull c) {
    ull d; asm("fma.rn.f32x2 %0, %1, %2, %3;" : "=l"(d) : "l"(a), "l"(b), "l"(c)); return d;
}
__device__ __forceinline__ ull mul2(ull a, ull b) {
    ull r; asm("mul.rn.f32x2 %0, %1, %2;" : "=l"(r) : "l"(a), "l"(b)); return r;
}
__device__ __forceinline__ ull shflup64(ull v) {
    unsigned lo = (unsigned)v, hi = (unsigned)(v >> 32);
    lo = __shfl_up_sync(0xffffffffu, lo, 1);
    hi = __shfl_up_sync(0xffffffffu, hi, 1);
    return ((ull)hi << 32) | lo;
}
__device__ __forceinline__ int iclampi(int v, int lo, int hi) {
    return v < lo ? lo : (v > hi ? hi : v);
}

// Accumulate conv over 16 cin for this thread's 4 segments x 4 couts.
// acc[q][2s+j] = f32x2 partial for couts coq*4+q, x-pair j of segment s.
template<bool GLOB>
__device__ __forceinline__ void conv_accum(
    const float* __restrict__ src, int T0, int baset, int coq,
    const float* __restrict__ ws, ull acc[4][8])
{
    const int lane = threadIdx.x & 31;
    #pragma unroll 2
    for (int ci = 0; ci < 16; ++ci) {
        const float* row = src + (size_t)ci * (GLOB ? L : TILE);
        ull a0[4], a1[4], am[4], o0[4], o1[4], o2[4], ap[4];
        #pragma unroll
        for (int s = 0; s < 4; ++s) {
            const int t = baset + 128 * s;
            float4 v;
            if (GLOB) {
                int gx = iclampi(T0 + t, 0, L - 4);
                v = *(const float4*)(row + gx);
            } else {
                v = *(const float4*)(row + t);
            }
            a0[s] = pk2(v.x, v.y); a1[s] = pk2(v.z, v.w);
            ull amv = shflup64(a1[s]);
            float vp4 = __shfl_down_sync(0xffffffffu, v.x, 1);
            float vp5 = __shfl_down_sync(0xffffffffu, v.y, 1);
            if (lane == 0) {
                float2 e;
                if (GLOB) { int gx = iclampi(T0 + t - 2, 0, L - 2); e = *(const float2*)(row + gx); }
                else      { int tc = (t - 2 < 0) ? 0 : t - 2;       e = *(const float2*)(row + tc); }
                amv = pk2(e.x, e.y);
            }
            if (lane == 31) {
                float2 e;
                if (GLOB) { int gx = iclampi(T0 + t + 4, 0, L - 2); e = *(const float2*)(row + gx); }
                else      { int tc = (t + 4 > TILE - 2) ? TILE - 2 : t + 4; e = *(const float2*)(row + tc); }
                vp4 = e.x; vp5 = e.y;
            }
            am[s] = amv;
            float vm2f, vm1f; upk2(amv, vm2f, vm1f);
            o0[s] = pk2(vm1f, v.x);
            o1[s] = pk2(v.y, v.z);
            o2[s] = pk2(v.w, vp4);
            ap[s] = pk2(vp4, vp5);
        }
        #pragma unroll
        for (int q = 0; q < 4; ++q) {
            const float* wp = ws + (ci * 16 + coq * 4 + q) * 8;
            float4 wA = *(const float4*)wp;
            float w4f = wp[4];
            ull W0 = pk2(wA.x, wA.x), W1 = pk2(wA.y, wA.y), W2 = pk2(wA.z, wA.z),
                W3 = pk2(wA.w, wA.w), W4 = pk2(w4f, w4f);
            #pragma unroll
            for (int s = 0; s < 4; ++s) {
                fma2(acc[q][2*s],   am[s], W0);
                fma2(acc[q][2*s],   o0[s], W1);
                fma2(acc[q][2*s],   a0[s], W2);
                fma2(acc[q][2*s],   o1[s], W3);
                fma2(acc[q][2*s],   a1[s], W4);
                fma2(acc[q][2*s+1], a0[s], W0);
                fma2(acc[q][2*s+1], o1[s], W1);
                fma2(acc[q][2*s+1], a1[s], W2);
                fma2(acc[q][2*s+1], o2[s], W3);
                fma2(acc[q][2*s+1], ap[s], W4);
            }
        }
    }
}

// Edge-tile ghost fixups on a smem stage buffer.
// left (tile 0):  t in [0,18)   := value at t=18  (global x=10)
// right(tile 8):  t in [126,144):= value at t=125 (global x=8181)
__device__ __forceinline__ void fix_left(float* k) {
    for (int i = threadIdx.x; i < 16 * 18; i += NTHREADS) {
        int r = i / 18, t = i % 18;
        k[r * TILE + t] = k[r * TILE + 18];
    }
}
__device__ __forceinline__ void fix_right(float* k) {
    for (int i = threadIdx.x; i < 16 * 18; i += NTHREADS) {
        int r = i / 18, t = 126 + i % 18;
        k[r * TILE + t] = k[r * TILE + 125];
    }
}

__global__ void __launch_bounds__(NTHREADS, 1)
rk3_fused(const float* __restrict__ zsrc, float* __restrict__ dst,
          const float* __restrict__ W)
{
    extern __shared__ float sm[];
    float* k1 = sm;                       // 16 * 1024
    float* k2 = k1 + 16 * TILE;           // 16 * 1024
    float* ws = k2 + 16 * TILE;           // 16*16*8

    const int tid  = threadIdx.x;
    const int lane = tid & 31;
    const int w    = tid >> 5;
    const int coq  = w & 3;               // cout quad: couts 4*coq .. +3
    const int xh   = w >> 2;              // x half (0/1)
    const int tile = blockIdx.x;
    const int b    = blockIdx.y;
    const int T0   = tile * COMMIT - 8;
    const int baset = xh * 512 + 4 * lane;

    const float* gz   = zsrc + (size_t)b * CHN * L;
    float*       gdst = dst  + (size_t)b * CHN * L;

    for (int i = tid; i < 16 * 16 * 5; i += NTHREADS) {
        int co = i / 80, r = i % 80, ci = r / 5, t = r % 5;
        ws[(ci * 16 + co) * 8 + t] = W[i];
    }
    __syncthreads();

    const ull hdup = pk2(HSTEP, HSTEP);
    const ull qh   = pk2(0.25f * HSTEP, 0.25f * HSTEP);
    const ull qd   = pk2(0.25f, 0.25f);
    const ull tq   = pk2(0.75f, 0.75f);
    const ull c13  = pk2(1.0f/3.0f, 1.0f/3.0f);
    const ull c23  = pk2(2.0f/3.0f, 2.0f/3.0f);
    const ull c2h3 = pk2(2.0f*HSTEP/3.0f, 2.0f*HSTEP/3.0f);

    ull acc[4][8];

    // ================= stage 1: k1 = B(z + h conv(z)) =================
    #pragma unroll
    for (int q = 0; q < 4; ++q)
        #pragma unroll
        for (int j = 0; j < 8; ++j) acc[q][j] = 0ull;
    conv_accum<true>(gz, T0, baset, coq, ws, acc);
    #pragma unroll
    for (int q = 0; q < 4; ++q) {
        const int co = coq * 4 + q;
        const float* zrow = gz + (size_t)co * L;
        float* krow = k1 + co * TILE;
        #pragma unroll
        for (int s = 0; s < 4; ++s) {
            const int t = baset + 128 * s;
            int gx = iclampi(T0 + t, 0, L - 4);
            float4 zv = *(const float4*)(zrow + gx);
            ull r0 = fma2g(acc[q][2*s],   hdup, pk2(zv.x, zv.y));
            ull r1 = fma2g(acc[q][2*s+1], hdup, pk2(zv.z, zv.w));
            float f0,f1,f2,f3; upk2(r0,f0,f1); upk2(r1,f2,f3);
            *(float4*)(krow + t) = make_float4(f0,f1,f2,f3);
        }
    }
    __syncthreads();
    if (tile == 0)      fix_left(k1);
    if (tile == NT - 1) fix_right(k1);
    __syncthreads();

    // ======== stage 2: k2 = B(0.75 z + 0.25 k1 + 0.25 h conv(k1)) ========
    #pragma unroll
    for (int q = 0; q < 4; ++q)
        #pragma unroll
        for (int j = 0; j < 8; ++j) acc[q][j] = 0ull;
    conv_accum<false>(k1, T0, baset, coq, ws, acc);
    #pragma unroll
    for (int q = 0; q < 4; ++q) {
        const int co = coq * 4 + q;
        const float* zrow = gz + (size_t)co * L;
        const float* k1row = k1 + co * TILE;
        float* k2row = k2 + co * TILE;
        #pragma unroll
        for (int s = 0; s < 4; ++s) {
            const int t = baset + 128 * s;
            int gx = iclampi(T0 + t, 0, L - 4);
            float4 zv = *(const float4*)(zrow + gx);
            float4 kv = *(const float4*)(k1row + t);
            ull r0 = mul2(acc[q][2*s], qh);
            r0 = fma2g(pk2(kv.x, kv.y), qd, r0);
            r0 = fma2g(pk2(zv.x, zv.y), tq, r0);
            ull r1 = mul2(acc[q][2*s+1], qh);
            r1 = fma2g(pk2(kv.z, kv.w), qd, r1);
            r1 = fma2g(pk2(zv.z, zv.w), tq, r1);
            float f0,f1,f2,f3; upk2(r0,f0,f1); upk2(r1,f2,f3);
            *(float4*)(k2row + t) = make_float4(f0,f1,f2,f3);
        }
    }
    __syncthreads();
    if (tile == 0)      fix_left(k2);
    if (tile == NT - 1) fix_right(k2);
    __syncthreads();

    // ======== stage 3: out = B(z/3 + 2 k2/3 + (2h/3) conv(k2)) ========
    #pragma unroll
    for (int q = 0; q < 4; ++q)
        #pragma unroll
        for (int j = 0; j < 8; ++j) acc[q][j] = 0ull;
    conv_accum<false>(k2, T0, baset, coq, ws, acc);

    const bool lwr = (tile == 0)      && (xh == 0) && (lane == 4);   // owns t=16..19 (x=8..11)
    const bool rwr = (tile == NT - 1) && (xh == 0) && (lane == 31);  // owns t=124..127 (x=8180..8183)

    #pragma unroll
    for (int q = 0; q < 4; ++q) {
        const int co = coq * 4 + q;
        const float* zrow = gz + (size_t)co * L;
        const float* k2row = k2 + co * TILE;
        float* orow = gdst + (size_t)co * L;
        #pragma unroll
        for (int s = 0; s < 4; ++s) {
            const int t = baset + 128 * s;
            const int x0 = T0 + t;
            int gx = iclampi(x0, 0, L - 4);
            float4 zv = *(const float4*)(zrow + gx);
            float4 kv = *(const float4*)(k2row + t);
            ull r0 = mul2(acc[q][2*s], c2h3);
            r0 = fma2g(pk2(kv.x, kv.y), c23, r0);
            r0 = fma2g(pk2(zv.x, zv.y), c13, r0);
            ull r1 = mul2(acc[q][2*s+1], c2h3);
            r1 = fma2g(pk2(kv.z, kv.w), c23, r1);
            r1 = fma2g(pk2(zv.z, zv.w), c13, r1);
            float f0,f1,f2,f3; upk2(r0,f0,f1); upk2(r1,f2,f3);
            if (x0 >= 12 && x0 <= 8176 && t >= 8 && t < 8 + COMMIT)
                *(float4*)(orow + x0) = make_float4(f0,f1,f2,f3);
            if (s == 0 && lwr) {
                // f2 = x=10 interior value; ghosts [0,10) := f2; also commit x=10,11
                #pragma unroll
                for (int i = 0; i < 10; ++i) orow[i] = f2;
                orow[10] = f2; orow[11] = f3;
            }
            if (s == 0 && rwr) {
                // f0,f1 = x=8180,8181; ghosts [8182,8192) := f1
                orow[8180] = f0; orow[8181] = f1;
                #pragma unroll
                for (int i = 0; i < 10; ++i) orow[8182 + i] = f1;
            }
        }
    }
}

extern "C" void kernel_launch(void* const* d_in, const int* in_sizes, int n_in,
                              void* d_out, int out_size) {
    const float* z0 = (const float*)d_in[0];
    const float* W  = (const float*)d_in[1];
    float* out = (float*)d_out;

    float* zscr;
    cudaGetSymbolAddress((void**)&zscr, g_scratch);

    const size_t smem_bytes = (size_t)(2 * 16 * TILE + 16 * 16 * 8) * sizeof(float); // 139264
    cudaFuncSetAttribute(rk3_fused, cudaFuncAttributeMaxDynamicSharedMemorySize,
                         (int)smem_bytes);

    dim3 grid(NT, BATCH);
    for (int s = 0; s < NSTEPS; ++s) {
        const float* src;
        float* dst;
        if (s == 0)     { src = z0;   dst = zscr; }
        else if (s & 1) { src = zscr; dst = out;  }
        else            { src = out;  dst = zscr; }
        rk3_fused<<<grid, NTHREADS, smem_bytes>>>(src, dst, W);
    }
}

// round 5
// speedup vs baseline: 1.2670x; 1.2670x over previous
#include <cuda_runtime.h>
#include <cstdint>

#define L       8192
#define CHN     16
#define BATCH   32
#define NSTEPS  100
#define HSTEP   0.01f

typedef unsigned long long ull;

__device__ float g_z [(size_t)BATCH * CHN * L];
__device__ float g_k1[(size_t)BATCH * CHN * L];
__device__ float g_k2[(size_t)BATCH * CHN * L];

__device__ __forceinline__ ull pk2(float lo, float hi) {
    ull r; asm("mov.b64 %0, {%1,%2};" : "=l"(r) : "f"(lo), "f"(hi)); return r;
}
__device__ __forceinline__ void upk2(ull a, float& lo, float& hi) {
    asm("mov.b64 {%0,%1}, %2;" : "=f"(lo), "=f"(hi) : "l"(a));
}
__device__ __forceinline__ void fma2(ull &acc, ull a, ull b) {
    asm("fma.rn.f32x2 %0, %1, %2, %0;" : "+l"(acc) : "l"(a), "l"(b));
}
__device__ __forceinline__ ull fma2g(ull a, ull b, ull c) {
    ull d; asm("fma.rn.f32x2 %0, %1, %2, %3;" : "=l"(d) : "l"(a), "l"(b), "l"(c)); return d;
}
__device__ __forceinline__ ull mul2(ull a, ull b) {
    ull r; asm("mul.rn.f32x2 %0, %1, %2;" : "=l"(r) : "l"(a), "l"(b)); return r;
}

// Per-output-chunk store with ghost-cell handling.
// Valid interior formula holds for x in [10, 8181]; ghosts copy those edges.
__device__ __forceinline__ void store_chunk(float* __restrict__ orow, int x,
                                            float f0, float f1, float f2, float f3) {
    if (x >= 12 && x <= 8176) {
        *(float4*)(orow + x) = make_float4(f0, f1, f2, f3);
    } else if (x == 8) {
        // f2 = out[10], f3 = out[11]; ghosts [0,10) := out[10]
        #pragma unroll
        for (int i = 0; i < 10; ++i) orow[i] = f2;
        orow[10] = f2; orow[11] = f3;
    } else if (x == 8180) {
        // f0 = out[8180], f1 = out[8181]; ghosts [8182,8192) := out[8181]
        orow[8180] = f0; orow[8181] = f1;
        #pragma unroll
        for (int i = 0; i < 10; ++i) orow[8182 + i] = f1;
    }
    // x in {0,4,8184,8188}: covered by the ghost writes above
}

// STAGE 1: out = B(z + h conv(z))
// STAGE 2: out = B(0.75 z + 0.25 k + 0.25 h conv(k))
// STAGE 3: out = B(z/3 + 2k/3 + (2h/3) conv(k))
template<int STAGE>
__global__ void __launch_bounds__(256, 2)
stage_k(const float* __restrict__ zin, const float* __restrict__ kin,
        float* __restrict__ out, const float* __restrict__ Wg)
{
    // wd[ci][co][12] : [w0,w0,w1,w1][w2,w2,w3,w3][w4,w4,-,-]  (48B per co, 16B aligned)
    __shared__ float wd[CHN * CHN * 12];
    const int tid = threadIdx.x;
    for (int i = tid; i < CHN * CHN * 5; i += 256) {
        int co = i / 80, r = i % 80, ci = r / 5, t = r % 5;
        float w = Wg[i];
        int base = (ci * 16 + co) * 12;
        wd[base + 2 * t]     = w;
        wd[base + 2 * t + 1] = w;
    }
    __syncthreads();

    const int lane = tid & 31;
    const int w    = tid >> 5;
    const int coo  = (w & 1) * 8;          // cout base (0 or 8)
    const int sp   = w >> 1;               // segment pair id 0..3
    const int b    = blockIdx.y;
    const int X0   = blockIdx.x * 1024;

    const int xA = X0 + sp * 128 + 4 * lane;  // segment A chunk
    const int xB = xA + 512;                  // segment B chunk

    // clamped conv-window load offsets (clamping corrupts only ghost chunks)
    const int aA0 = (xA - 4 < 0) ? 0 : xA - 4;
    const int aA1 = xA;
    const int aA2 = xA + 4;                   // xA+4 <= 8188-512+4... always <= 8188? xA<=7676 -> ok
    const int aB0 = xB - 4;
    const int aB1 = xB;
    const int aB2 = (xB + 4 > L - 4) ? L - 4 : xB + 4;

    const float* csrc = (STAGE == 1 ? zin : kin) + (size_t)b * CHN * L;

    ull acc[8][4];   // [co][0,1 = segA pairs; 2,3 = segB pairs]
    #pragma unroll
    for (int q = 0; q < 8; ++q)
        #pragma unroll
        for (int j = 0; j < 4; ++j) acc[q][j] = 0ull;

    const float* row = csrc;
    #pragma unroll 1
    for (int ci = 0; ci < CHN; ++ci, row += L) {
        float4 A0 = *(const float4*)(row + aA0);
        float4 A1 = *(const float4*)(row + aA1);
        float4 A2 = *(const float4*)(row + aA2);
        float4 B0 = *(const float4*)(row + aB0);
        float4 B1 = *(const float4*)(row + aB1);
        float4 B2 = *(const float4*)(row + aB2);

        ull Aam = pk2(A0.z, A0.w), Ao0 = pk2(A0.w, A1.x);
        ull Aa0 = pk2(A1.x, A1.y), Ao1 = pk2(A1.y, A1.z);
        ull Aa1 = pk2(A1.z, A1.w), Ao2 = pk2(A1.w, A2.x);
        ull Aa2 = pk2(A2.x, A2.y);
        ull Bam = pk2(B0.z, B0.w), Bo0 = pk2(B0.w, B1.x);
        ull Ba0 = pk2(B1.x, B1.y), Bo1 = pk2(B1.y, B1.z);
        ull Ba1 = pk2(B1.z, B1.w), Bo2 = pk2(B1.w, B2.x);
        ull Ba2 = pk2(B2.x, B2.y);

        const float* wrow = &wd[(ci * 16 + coo) * 12];
        #pragma unroll
        for (int q = 0; q < 8; ++q) {
            ulonglong2 u01 = *(const ulonglong2*)(wrow + q * 12);
            ulonglong2 u23 = *(const ulonglong2*)(wrow + q * 12 + 4);
            ull W4 = *(const ull*)(wrow + q * 12 + 8);
            ull W0 = u01.x, W1 = u01.y, W2 = u23.x, W3 = u23.y;

            fma2(acc[q][0], Aam, W0); fma2(acc[q][0], Ao0, W1);
            fma2(acc[q][0], Aa0, W2); fma2(acc[q][0], Ao1, W3);
            fma2(acc[q][0], Aa1, W4);
            fma2(acc[q][1], Aa0, W0); fma2(acc[q][1], Ao1, W1);
            fma2(acc[q][1], Aa1, W2); fma2(acc[q][1], Ao2, W3);
            fma2(acc[q][1], Aa2, W4);

            fma2(acc[q][2], Bam, W0); fma2(acc[q][2], Bo0, W1);
            fma2(acc[q][2], Ba0, W2); fma2(acc[q][2], Bo1, W3);
            fma2(acc[q][2], Ba1, W4);
            fma2(acc[q][3], Ba0, W0); fma2(acc[q][3], Bo1, W1);
            fma2(acc[q][3], Ba1, W2); fma2(acc[q][3], Bo2, W3);
            fma2(acc[q][3], Ba2, W4);
        }
    }

    // ---- epilogue ----
    const float ca = (STAGE == 1) ? 1.0f  : (STAGE == 2) ? 0.75f         : (1.0f / 3.0f);
    const float cb = (STAGE == 1) ? 0.0f  : (STAGE == 2) ? 0.25f         : (2.0f / 3.0f);
    const float cc = (STAGE == 1) ? HSTEP : (STAGE == 2) ? 0.25f * HSTEP : (2.0f * HSTEP / 3.0f);

    const float* zb = zin + (size_t)b * CHN * L;
    const float* kb = (STAGE == 1) ? nullptr : kin + (size_t)b * CHN * L;
    float*       ob = out + (size_t)b * CHN * L;

    #pragma unroll
    for (int q = 0; q < 8; ++q) {
        const int co = coo + q;
        const float* zrow = zb + (size_t)co * L;
        float*       orow = ob + (size_t)co * L;

        #pragma unroll
        for (int s = 0; s < 2; ++s) {
            const int x = (s == 0) ? xA : xB;
            float c0, c1, c2, c3;
            upk2(acc[q][2 * s],     c0, c1);
            upk2(acc[q][2 * s + 1], c2, c3);

            float4 zv = *(const float4*)(zrow + x);
            float r0, r1, r2, r3;
            if (STAGE == 1) {
                r0 = fmaf(cc, c0, zv.x); r1 = fmaf(cc, c1, zv.y);
                r2 = fmaf(cc, c2, zv.z); r3 = fmaf(cc, c3, zv.w);
            } else {
                float4 kv = *(const float4*)(kb + (size_t)co * L + x);
                r0 = fmaf(ca, zv.x, fmaf(cb, kv.x, cc * c0));
                r1 = fmaf(ca, zv.y, fmaf(cb, kv.y, cc * c1));
                r2 = fmaf(ca, zv.z, fmaf(cb, kv.z, cc * c2));
                r3 = fmaf(ca, zv.w, fmaf(cb, kv.w, cc * c3));
            }
            store_chunk(orow, x, r0, r1, r2, r3);
        }
    }
}

extern "C" void kernel_launch(void* const* d_in, const int* in_sizes, int n_in,
                              void* d_out, int out_size) {
    const float* z0 = (const float*)d_in[0];
    const float* W  = (const float*)d_in[1];
    float* out = (float*)d_out;

    float *zscr, *k1, *k2;
    cudaGetSymbolAddress((void**)&zscr, g_z);
    cudaGetSymbolAddress((void**)&k1,   g_k1);
    cudaGetSymbolAddress((void**)&k2,   g_k2);

    dim3 grid(L / 1024, BATCH);   // (8, 32) = 256 blocks
    for (int s = 0; s < NSTEPS; ++s) {
        const float* src;
        float* dst;
        if (s == 0)      { src = z0;   dst = zscr; }
        else if (s & 1)  { src = zscr; dst = out;  }
        else             { src = out;  dst = zscr; }

        stage_k<1><<<grid, 256>>>(src, src, k1, W);
        stage_k<2><<<grid, 256>>>(src, k1,  k2, W);
        stage_k<3><<<grid, 256>>>(src, k2,  dst, W);
    }
}

// round 6
// speedup vs baseline: 1.6717x; 1.3194x over previous
#include <cuda_runtime.h>
#include <cstdint>

#define L       8192
#define CHN     16
#define BATCH   32
#define NSTEPS  100
#define HSTEP   0.01f

typedef unsigned long long ull;

__device__ float g_z [(size_t)BATCH * CHN * L];
__device__ float g_k1[(size_t)BATCH * CHN * L];
__device__ float g_k2[(size_t)BATCH * CHN * L];

__device__ __forceinline__ ull pk2(float lo, float hi) {
    ull r; asm("mov.b64 %0, {%1,%2};" : "=l"(r) : "f"(lo), "f"(hi)); return r;
}
__device__ __forceinline__ void upk2(ull a, float& lo, float& hi) {
    asm("mov.b64 {%0,%1}, %2;" : "=f"(lo), "=f"(hi) : "l"(a));
}
__device__ __forceinline__ void fma2(ull &acc, ull a, ull b) {
    asm("fma.rn.f32x2 %0, %1, %2, %0;" : "+l"(acc) : "l"(a), "l"(b));
}

// Per-output-chunk store with ghost-cell handling.
// Valid interior formula holds for x in [10, 8181]; ghosts copy those edges.
__device__ __forceinline__ void store_chunk(float* __restrict__ orow, int x,
                                            float f0, float f1, float f2, float f3) {
    if (x >= 12 && x <= 8176) {
        *(float4*)(orow + x) = make_float4(f0, f1, f2, f3);
    } else if (x == 8) {
        #pragma unroll
        for (int i = 0; i < 10; ++i) orow[i] = f2;
        orow[10] = f2; orow[11] = f3;
    } else if (x == 8180) {
        orow[8180] = f0; orow[8181] = f1;
        #pragma unroll
        for (int i = 0; i < 10; ++i) orow[8182 + i] = f1;
    }
}

// STAGE 1: out = B(z + h conv(z))
// STAGE 2: out = B(0.75 z + 0.25 k + 0.25 h conv(k))
// STAGE 3: out = B(z/3 + 2k/3 + (2h/3) conv(k))
template<int STAGE>
__global__ void __launch_bounds__(256, 2)
stage_k(const float* __restrict__ zin, const float* __restrict__ kin,
        float* __restrict__ out, const float* __restrict__ Wg)
{
    // wd[ci][co][12] : [w0,w0,w1,w1][w2,w2,w3,w3][w4,w4,-,-]
    __shared__ float wd[CHN * CHN * 12];
    const int tid = threadIdx.x;
    for (int i = tid; i < CHN * CHN * 5; i += 256) {
        int co = i / 80, r = i % 80, ci = r / 5, t = r % 5;
        float w = Wg[i];
        int base = (ci * 16 + co) * 12;
        wd[base + 2 * t]     = w;
        wd[base + 2 * t + 1] = w;
    }
    __syncthreads();

    const int lane = tid & 31;
    const int w    = tid >> 5;
    const int coo  = (w & 1) * 8;          // cout base (0 or 8)
    const int sp   = w >> 1;               // segment pair id 0..3
    const int b    = blockIdx.y;
    const int X0   = blockIdx.x * 1024;

    const int xA = X0 + sp * 128 + 4 * lane;  // segment A chunk
    const int xB = xA + 512;                  // segment B chunk

    const int aA0 = (xA - 4 < 0) ? 0 : xA - 4;
    const int aB2 = (xB + 4 > L - 4) ? L - 4 : xB + 4;

    const float* csrc = (STAGE == 1 ? zin : kin) + (size_t)b * CHN * L;

    ull acc[8][4];   // acc[q][p]: lo = out[coo+q][xA+p], hi = out[coo+q][xB+p]
    #pragma unroll
    for (int q = 0; q < 8; ++q)
        #pragma unroll
        for (int j = 0; j < 4; ++j) acc[q][j] = 0ull;

    const float* rowp = csrc;
    float4 cA0 = *(const float4*)(rowp + aA0);
    float4 cA1 = *(const float4*)(rowp + xA);
    float4 cA2 = *(const float4*)(rowp + xA + 4);
    float4 cB0 = *(const float4*)(rowp + xB - 4);
    float4 cB1 = *(const float4*)(rowp + xB);
    float4 cB2 = *(const float4*)(rowp + aB2);

    #pragma unroll 1
    for (int ci = 0; ci < CHN; ++ci) {
        const float* nrow = rowp + L;
        float4 nA0, nA1, nA2, nB0, nB1, nB2;
        if (ci < CHN - 1) {                       // predicated prefetch
            nA0 = *(const float4*)(nrow + aA0);
            nA1 = *(const float4*)(nrow + xA);
            nA2 = *(const float4*)(nrow + xA + 4);
            nB0 = *(const float4*)(nrow + xB - 4);
            nB1 = *(const float4*)(nrow + xB);
            nB2 = *(const float4*)(nrow + aB2);
        }

        // window pairs: P[j] = (vA[xA-2+j], vB[xB-2+j]), each value used once
        ull P0 = pk2(cA0.z, cB0.z), P1 = pk2(cA0.w, cB0.w);
        ull P2 = pk2(cA1.x, cB1.x), P3 = pk2(cA1.y, cB1.y);
        ull P4 = pk2(cA1.z, cB1.z), P5 = pk2(cA1.w, cB1.w);
        ull P6 = pk2(cA2.x, cB2.x), P7 = pk2(cA2.y, cB2.y);

        const float* wrow = &wd[(ci * 16 + coo) * 12];
        #pragma unroll
        for (int q = 0; q < 8; ++q) {
            ulonglong2 u01 = *(const ulonglong2*)(wrow + q * 12);
            ulonglong2 u23 = *(const ulonglong2*)(wrow + q * 12 + 4);
            ull W4 = *(const ull*)(wrow + q * 12 + 8);
            ull W0 = u01.x, W1 = u01.y, W2 = u23.x, W3 = u23.y;

            fma2(acc[q][0], P0, W0); fma2(acc[q][0], P1, W1);
            fma2(acc[q][0], P2, W2); fma2(acc[q][0], P3, W3);
            fma2(acc[q][0], P4, W4);
            fma2(acc[q][1], P1, W0); fma2(acc[q][1], P2, W1);
            fma2(acc[q][1], P3, W2); fma2(acc[q][1], P4, W3);
            fma2(acc[q][1], P5, W4);
            fma2(acc[q][2], P2, W0); fma2(acc[q][2], P3, W1);
            fma2(acc[q][2], P4, W2); fma2(acc[q][2], P5, W3);
            fma2(acc[q][2], P6, W4);
            fma2(acc[q][3], P3, W0); fma2(acc[q][3], P4, W1);
            fma2(acc[q][3], P5, W2); fma2(acc[q][3], P6, W3);
            fma2(acc[q][3], P7, W4);
        }
        cA0 = nA0; cA1 = nA1; cA2 = nA2;
        cB0 = nB0; cB1 = nB1; cB2 = nB2;
        rowp = nrow;
    }

    // ---- epilogue ----
    const float ca = (STAGE == 1) ? 1.0f  : (STAGE == 2) ? 0.75f         : (1.0f / 3.0f);
    const float cb = (STAGE == 1) ? 0.0f  : (STAGE == 2) ? 0.25f         : (2.0f / 3.0f);
    const float cc = (STAGE == 1) ? HSTEP : (STAGE == 2) ? 0.25f * HSTEP : (2.0f * HSTEP / 3.0f);

    const float* zb = zin + (size_t)b * CHN * L;
    const float* kb = (STAGE == 1) ? nullptr : kin + (size_t)b * CHN * L;
    float*       ob = out + (size_t)b * CHN * L;

    #pragma unroll
    for (int q = 0; q < 8; ++q) {
        const int co = coo + q;
        const float* zrow = zb + (size_t)co * L;
        float*       orow = ob + (size_t)co * L;

        float cvA[4], cvB[4];
        #pragma unroll
        for (int p = 0; p < 4; ++p) upk2(acc[q][p], cvA[p], cvB[p]);

        #pragma unroll
        for (int s = 0; s < 2; ++s) {
            const int x = (s == 0) ? xA : xB;
            const float* cv = (s == 0) ? cvA : cvB;

            float4 zv = *(const float4*)(zrow + x);
            float r0, r1, r2, r3;
            if (STAGE == 1) {
                r0 = fmaf(cc, cv[0], zv.x); r1 = fmaf(cc, cv[1], zv.y);
                r2 = fmaf(cc, cv[2], zv.z); r3 = fmaf(cc, cv[3], zv.w);
            } else {
                float4 kv = *(const float4*)(kb + (size_t)co * L + x);
                r0 = fmaf(ca, zv.x, fmaf(cb, kv.x, cc * cv[0]));
                r1 = fmaf(ca, zv.y, fmaf(cb, kv.y, cc * cv[1]));
                r2 = fmaf(ca, zv.z, fmaf(cb, kv.z, cc * cv[2]));
                r3 = fmaf(ca, zv.w, fmaf(cb, kv.w, cc * cv[3]));
            }
            store_chunk(orow, x, r0, r1, r2, r3);
        }
    }
}

extern "C" void kernel_launch(void* const* d_in, const int* in_sizes, int n_in,
                              void* d_out, int out_size) {
    const float* z0 = (const float*)d_in[0];
    const float* W  = (const float*)d_in[1];
    float* out = (float*)d_out;

    float *zscr, *k1, *k2;
    cudaGetSymbolAddress((void**)&zscr, g_z);
    cudaGetSymbolAddress((void**)&k1,   g_k1);
    cudaGetSymbolAddress((void**)&k2,   g_k2);

    dim3 grid(L / 1024, BATCH);   // (8, 32) = 256 blocks
    for (int s = 0; s < NSTEPS; ++s) {
        const float* src;
        float* dst;
        if (s == 0)      { src = z0;   dst = zscr; }
        else if (s & 1)  { src = zscr; dst = out;  }
        else             { src = out;  dst = zscr; }

        stage_k<1><<<grid, 256>>>(src, src, k1, W);
        stage_k<2><<<grid, 256>>>(src, k1,  k2, W);
        stage_k<3><<<grid, 256>>>(src, k2,  dst, W);
    }
}